// round 9
// baseline (speedup 1.0000x reference)
#include <cuda_runtime.h>
#include <mma.h>
#include <cstdint>

using namespace nvcuda;

// ---------------- weight layout (floats), strides 68 / 20, all conflict-free --
#define OFF_COL0 0          // [64][68]
#define OFF_VIS0 4352       // [48][68]
#define OFF_SIG0 7616       // [32][68]
#define OFF_C1A  9792       // [64][68] col1 rows 0..63
#define OFF_C1B  14144      // [16][68] row0=0, rows1..15 = col1 rows 64..78
#define OFF_SIG1 15232      // [64][20]
#define OFF_VIS1 16512      // [64][20] col0 real
#define OFF_COL2 17792      // [64][20] cols 0..2 real
#define W_TOTAL  19072

__device__ __align__(16) float g_W[W_TOTAL];

__device__ __forceinline__ float tf32r(float x) {
    unsigned u;
    asm("cvt.rna.tf32.f32 %0, %1;" : "=r"(u) : "f"(x));
    return __uint_as_float(u);
}

__global__ void prep_kernel(const float* __restrict__ ws0, const float* __restrict__ ws1,
                            const float* __restrict__ wc0, const float* __restrict__ wc1,
                            const float* __restrict__ wc2, const float* __restrict__ wv0,
                            const float* __restrict__ wv1) {
    int t = threadIdx.x;
    for (int i = t; i < W_TOTAL; i += 256) g_W[i] = 0.f;
    __syncthreads();
    for (int i = t; i < 64 * 64; i += 256) { int k = i >> 6, n = i & 63; g_W[OFF_COL0 + k * 68 + n] = tf32r(wc0[i]); }
    for (int i = t; i < 48 * 64; i += 256) { int k = i >> 6, n = i & 63; g_W[OFF_VIS0 + k * 68 + n] = tf32r(wv0[i]); }
    for (int i = t; i < 32 * 64; i += 256) { int k = i >> 6, n = i & 63; g_W[OFF_SIG0 + k * 68 + n] = tf32r(ws0[i]); }
    for (int i = t; i < 64 * 64; i += 256) { int k = i >> 6, n = i & 63; g_W[OFF_C1A + k * 68 + n] = tf32r(wc1[i]); }
    for (int i = t; i < 15 * 64; i += 256) { int r = i / 64 + 1, n = i % 64; g_W[OFF_C1B + r * 68 + n] = tf32r(wc1[(63 + r) * 64 + n]); }
    for (int i = t; i < 64 * 16; i += 256) { int k = i >> 4, n = i & 15; g_W[OFF_SIG1 + k * 20 + n] = tf32r(ws1[i]); }
    for (int i = t; i < 64; i += 256)      { g_W[OFF_VIS1 + i * 20] = tf32r(wv1[i]); }
    for (int i = t; i < 64 * 3; i += 256)  { int k = i / 3, c = i - k * 3; g_W[OFF_COL2 + k * 20 + c] = tf32r(wc2[i]); }
}

// ---------------- SH degree-4 ----------------
__device__ __forceinline__ void sh16(float x, float y, float z, float* e) {
    float xx = x * x, yy = y * y, zz = z * z;
    float xy = x * y, yz = y * z, xz = x * z;
    e[0]  = 0.28209479177387814f;
    e[1]  = -0.48860251190291987f * y;
    e[2]  = 0.48860251190291987f * z;
    e[3]  = -0.48860251190291987f * x;
    e[4]  = 1.0925484305920792f * xy;
    e[5]  = -1.0925484305920792f * yz;
    e[6]  = 0.94617469575756f * zz - 0.31539156525252005f;
    e[7]  = -1.0925484305920792f * xz;
    e[8]  = 0.5462742152960396f * (xx - yy);
    e[9]  = 0.5900435899266435f * y * (3.0f * xx - yy);
    e[10] = 2.890611442640554f * xy * z;
    e[11] = 0.4570457994644657f * y * (4.0f * zz - xx - yy);
    e[12] = 0.3731763325901154f * z * (2.0f * zz - 3.0f * xx - 3.0f * yy);
    e[13] = 0.4570457994644657f * x * (4.0f * zz - xx - yy);
    e[14] = 1.445305721320277f * z * (xx - yy);
    e[15] = 0.5900435899266435f * x * (xx - 3.0f * yy);
}

// ---------------- smem layout (floats) ----------------
#define SM_BUFA  19072              // [128][68] inputs; later geo in cols 0..15
#define SM_SIGH  27776              // [128][68] sig_h; later col1_h
#define SM_VISH  36480              // [128][68] vis_h; later vis1 tile
#define SM_COLH  45184              // [128][68] col0_h; later col2 out
#define SM_VIS   53888              // [128]
#define SM_TOTAL 54016
#define SMEM_BYTES (SM_TOTAL * 4)

typedef wmma::fragment<wmma::matrix_a, 16, 16, 8, wmma::precision::tf32, wmma::row_major> FragA;
typedef wmma::fragment<wmma::matrix_b, 16, 16, 8, wmma::precision::tf32, wmma::row_major> FragB;
typedef wmma::fragment<wmma::accumulator, 16, 16, 8, float> FragC;

// group barrier: 256 threads, barrier id g+1
#define GBAR() asm volatile("bar.sync %0, %1;" :: "r"(g + 1), "r"(256) : "memory")

// one layer, both n-tiles as 2 parallel chains sharing hoisted A frags
template <int KS>
__device__ __forceinline__ void layer_dual(const FragA* a, const float* B,
                                           float* C, int rowM, int nt0) {
    FragC c0, c1;
    wmma::fill_fragment(c0, 0.f);
    wmma::fill_fragment(c1, 0.f);
#pragma unroll
    for (int k = 0; k < KS; k++) {
        FragB b0, b1;
        wmma::load_matrix_sync(b0, B + k * 8 * 68 + nt0 * 16, 68);
        wmma::load_matrix_sync(b1, B + k * 8 * 68 + nt0 * 16 + 16, 68);
        wmma::mma_sync(c0, a[k], b0, c0);
        wmma::mma_sync(c1, a[k], b1, c1);
    }
#pragma unroll
    for (int i = 0; i < c0.num_elements; i++) c0.x[i] = tf32r(fmaxf(c0.x[i], 0.f));
#pragma unroll
    for (int i = 0; i < c1.num_elements; i++) c1.x[i] = tf32r(fmaxf(c1.x[i], 0.f));
    wmma::store_matrix_sync(C + rowM * 68 + nt0 * 16, c0, 68, wmma::mem_row_major);
    wmma::store_matrix_sync(C + rowM * 68 + nt0 * 16 + 16, c1, 68, wmma::mem_row_major);
}

__global__ void __launch_bounds__(512, 1)
nerf_wmma(const float* __restrict__ x_feat, const float* __restrict__ dvec,
          const float* __restrict__ lvec, float* __restrict__ out,
          int N, int ntiles) {
    extern __shared__ float sm[];
    float* sW   = sm;
    float* bufA = sm + SM_BUFA;
    float* sigH = sm + SM_SIGH;
    float* visH = sm + SM_VISH;
    float* colH = sm + SM_COLH;
    float* visR = sm + SM_VIS;

    int tid = threadIdx.x, wid = tid >> 5;
    int g  = wid >> 3;          // group 0/1: warps 0-7 | 8-15
    int w8 = wid & 7;
    int blk = w8 >> 1, h = w8 & 1;
    int rowM = g * 64 + blk * 16;   // this warp's 16-row block
    int nt0 = 2 * h;                // first of the warp's two n-tiles
    int t2 = tid & 255;

    {
        const float4* s = (const float4*)g_W;
        float4* d = (float4*)sW;
        for (int i = tid; i < W_TOTAL / 4; i += 512) d[i] = s[i];
    }
    __syncthreads();

    for (int tile = blockIdx.x; tile < ntiles; tile += gridDim.x) {
        // ---- phase 0: group fills its 64 rows of bufA ----
        {
            int r = g * 64 + (t2 & 63);
            int p = tile * 128 + r;
            int pc = (p < N) ? p : (N - 1);
            if (t2 < 64) {
                const float4* xp = (const float4*)(x_feat + 32 * (size_t)pc);
                float* dst = bufA + r * 68;
#pragma unroll
                for (int i = 0; i < 8; i++) {
                    float4 v = xp[i];
                    dst[4 * i]     = tf32r(v.x);
                    dst[4 * i + 1] = tf32r(v.y);
                    dst[4 * i + 2] = tf32r(v.z);
                    dst[4 * i + 3] = tf32r(v.w);
                }
            } else if (t2 < 128) {
                float e[16];
                const float* lp = lvec + 3 * (size_t)pc;
                sh16(lp[0], lp[1], lp[2], e);
                float* dst = bufA + r * 68 + 32;
#pragma unroll
                for (int i = 0; i < 16; i++) dst[i] = tf32r(e[i]);
            } else if (t2 < 192) {
                float e[16];
                const float* dp = dvec + 3 * (size_t)pc;
                sh16(dp[0], dp[1], dp[2], e);
                float* dst = bufA + r * 68 + 48;
#pragma unroll
                for (int i = 0; i < 16; i++) dst[i] = tf32r(e[i]);
            }
        }
        GBAR();

        // ---- phase 1: A hoisted; each layer = 2 parallel n-tile chains ----
        {
            FragA a[8];
#pragma unroll
            for (int k = 0; k < 8; k++)
                wmma::load_matrix_sync(a[k], bufA + rowM * 68 + k * 8, 68);
            layer_dual<4>(a, sW + OFF_SIG0, sigH, rowM, nt0);
            layer_dual<6>(a, sW + OFF_VIS0, visH, rowM, nt0);
            layer_dual<8>(a, sW + OFF_COL0, colH, rowM, nt0);
        }
        GBAR();

        // ---- phase 2: h==0 -> sig1 (geo -> bufA cols 0..15); h==1 -> vis1 ----
        {
            const float* Ain = h ? visH : sigH;
            const float* Bw  = h ? (sW + OFF_VIS1) : (sW + OFF_SIG1);
            FragA a[8];
#pragma unroll
            for (int k = 0; k < 8; k++)
                wmma::load_matrix_sync(a[k], Ain + rowM * 68 + k * 8, 68);
            FragC c;
            wmma::fill_fragment(c, 0.f);
#pragma unroll
            for (int k = 0; k < 8; k++) {
                FragB b;
                wmma::load_matrix_sync(b, Bw + k * 8 * 20, 20);
                wmma::mma_sync(c, a[k], b, c);
            }
            if (h == 0) {   // geo: tf32-round, NO relu
#pragma unroll
                for (int i = 0; i < c.num_elements; i++) c.x[i] = tf32r(c.x[i]);
                wmma::store_matrix_sync(bufA + rowM * 68, c, 68, wmma::mem_row_major);
            } else {        // vis raw logit (col 0 real)
                wmma::store_matrix_sync(visH + rowM * 68, c, 68, wmma::mem_row_major);
            }
        }
        GBAR();
        if (t2 < 64) {
            int r = g * 64 + t2;
            visR[r] = __fdividef(1.f, 1.f + __expf(-visH[r * 68]));
        }

        // ---- phase 3: col1, 2 parallel n-tile chains sharing A ----
        {
            FragA a1[8], a2[2];
#pragma unroll
            for (int k = 0; k < 8; k++)
                wmma::load_matrix_sync(a1[k], colH + rowM * 68 + k * 8, 68);
#pragma unroll
            for (int k = 0; k < 2; k++)
                wmma::load_matrix_sync(a2[k], bufA + rowM * 68 + k * 8, 68);
            FragC c0, c1;
            wmma::fill_fragment(c0, 0.f);
            wmma::fill_fragment(c1, 0.f);
#pragma unroll
            for (int k = 0; k < 8; k++) {
                FragB b0, b1;
                wmma::load_matrix_sync(b0, sW + OFF_C1A + k * 8 * 68 + nt0 * 16, 68);
                wmma::load_matrix_sync(b1, sW + OFF_C1A + k * 8 * 68 + nt0 * 16 + 16, 68);
                wmma::mma_sync(c0, a1[k], b0, c0);
                wmma::mma_sync(c1, a1[k], b1, c1);
            }
#pragma unroll
            for (int k = 0; k < 2; k++) {
                FragB b0, b1;
                wmma::load_matrix_sync(b0, sW + OFF_C1B + k * 8 * 68 + nt0 * 16, 68);
                wmma::load_matrix_sync(b1, sW + OFF_C1B + k * 8 * 68 + nt0 * 16 + 16, 68);
                wmma::mma_sync(c0, a2[k], b0, c0);
                wmma::mma_sync(c1, a2[k], b1, c1);
            }
#pragma unroll
            for (int i = 0; i < c0.num_elements; i++) c0.x[i] = tf32r(fmaxf(c0.x[i], 0.f));
#pragma unroll
            for (int i = 0; i < c1.num_elements; i++) c1.x[i] = tf32r(fmaxf(c1.x[i], 0.f));
            wmma::store_matrix_sync(sigH + rowM * 68 + nt0 * 16, c0, 68, wmma::mem_row_major);
            wmma::store_matrix_sync(sigH + rowM * 68 + nt0 * 16 + 16, c1, 68, wmma::mem_row_major);
        }
        GBAR();

        // ---- phase 4: col2 (h==0 only) -> colH cols 0..15 (0..2 real, raw) ----
        if (h == 0) {
            FragA a[8];
#pragma unroll
            for (int k = 0; k < 8; k++)
                wmma::load_matrix_sync(a[k], sigH + rowM * 68 + k * 8, 68);
            FragC c;
            wmma::fill_fragment(c, 0.f);
#pragma unroll
            for (int k = 0; k < 8; k++) {
                FragB b;
                wmma::load_matrix_sync(b, sW + OFF_COL2 + k * 8 * 20, 20);
                wmma::mma_sync(c, a[k], b, c);
            }
            wmma::store_matrix_sync(colH + rowM * 68, c, 68, wmma::mem_row_major);
        }
        GBAR();

        // ---- epilogue: color = relu(col2) * sigmoid(vis), group's 64 rows ----
        for (int i = t2; i < 192; i += 256) {
            int pp = g * 64 + i / 3, c = i % 3;
            int gg = tile * 128 + pp;
            if (gg < N)
                out[3 * (size_t)gg + c] = fmaxf(colH[pp * 68 + c], 0.f) * visR[pp];
        }
        GBAR();
    }
}

extern "C" void kernel_launch(void* const* d_in, const int* in_sizes, int n_in,
                              void* d_out, int out_size) {
    const float* x_feat = (const float*)d_in[0];
    const float* dv     = (const float*)d_in[1];
    const float* lv     = (const float*)d_in[2];
    const float* w_sig0 = (const float*)d_in[3];
    const float* w_sig1 = (const float*)d_in[4];
    const float* w_col0 = (const float*)d_in[5];
    const float* w_col1 = (const float*)d_in[6];
    const float* w_col2 = (const float*)d_in[7];
    const float* w_vis0 = (const float*)d_in[8];
    const float* w_vis1 = (const float*)d_in[9];
    float* out = (float*)d_out;
    int N = in_sizes[0] / 32;
    int ntiles = (N + 127) / 128;

    int dev = 0, smc = 148;
    cudaGetDevice(&dev);
    cudaDeviceGetAttribute(&smc, cudaDevAttrMultiProcessorCount, dev);
    int grid = (smc < ntiles) ? smc : ntiles;

    cudaFuncSetAttribute(nerf_wmma, cudaFuncAttributeMaxDynamicSharedMemorySize,
                         SMEM_BYTES);

    prep_kernel<<<1, 256>>>(w_sig0, w_sig1, w_col0, w_col1, w_col2, w_vis0, w_vis1);
    nerf_wmma<<<grid, 512, SMEM_BYTES>>>(x_feat, dv, lv, out, N, ntiles);
}

// round 10
// speedup vs baseline: 1.1692x; 1.1692x over previous
#include <cuda_runtime.h>
#include <mma.h>
#include <cstdint>

using namespace nvcuda;

// ---------------- weight layout (floats), strides 68 / 20, all conflict-free --
#define OFF_COL0 0          // [64][68]
#define OFF_VIS0 4352       // [48][68]
#define OFF_SIG0 7616       // [32][68]
#define OFF_C1A  9792       // [64][68] col1 rows 0..63
#define OFF_C1B  14144      // [16][68] row0=0, rows1..15 = col1 rows 64..78
#define OFF_SIG1 15232      // [64][20]
#define OFF_VIS1 16512      // [64][20] col0 real
#define OFF_COL2 17792      // [64][20] cols 0..2 real
#define W_TOTAL  19072

__device__ __align__(16) float g_W[W_TOTAL];

__device__ __forceinline__ float tf32r(float x) {
    unsigned u;
    asm("cvt.rna.tf32.f32 %0, %1;" : "=r"(u) : "f"(x));
    return __uint_as_float(u);
}

__global__ void prep_kernel(const float* __restrict__ ws0, const float* __restrict__ ws1,
                            const float* __restrict__ wc0, const float* __restrict__ wc1,
                            const float* __restrict__ wc2, const float* __restrict__ wv0,
                            const float* __restrict__ wv1) {
    int t = threadIdx.x;
    for (int i = t; i < W_TOTAL; i += 256) g_W[i] = 0.f;
    __syncthreads();
    for (int i = t; i < 64 * 64; i += 256) { int k = i >> 6, n = i & 63; g_W[OFF_COL0 + k * 68 + n] = tf32r(wc0[i]); }
    for (int i = t; i < 48 * 64; i += 256) { int k = i >> 6, n = i & 63; g_W[OFF_VIS0 + k * 68 + n] = tf32r(wv0[i]); }
    for (int i = t; i < 32 * 64; i += 256) { int k = i >> 6, n = i & 63; g_W[OFF_SIG0 + k * 68 + n] = tf32r(ws0[i]); }
    for (int i = t; i < 64 * 64; i += 256) { int k = i >> 6, n = i & 63; g_W[OFF_C1A + k * 68 + n] = tf32r(wc1[i]); }
    for (int i = t; i < 15 * 64; i += 256) { int r = i / 64 + 1, n = i % 64; g_W[OFF_C1B + r * 68 + n] = tf32r(wc1[(63 + r) * 64 + n]); }
    for (int i = t; i < 64 * 16; i += 256) { int k = i >> 4, n = i & 15; g_W[OFF_SIG1 + k * 20 + n] = tf32r(ws1[i]); }
    for (int i = t; i < 64; i += 256)      { g_W[OFF_VIS1 + i * 20] = tf32r(wv1[i]); }
    for (int i = t; i < 64 * 3; i += 256)  { int k = i / 3, c = i - k * 3; g_W[OFF_COL2 + k * 20 + c] = tf32r(wc2[i]); }
}

// ---------------- SH degree-4 ----------------
__device__ __forceinline__ void sh16(float x, float y, float z, float* e) {
    float xx = x * x, yy = y * y, zz = z * z;
    float xy = x * y, yz = y * z, xz = x * z;
    e[0]  = 0.28209479177387814f;
    e[1]  = -0.48860251190291987f * y;
    e[2]  = 0.48860251190291987f * z;
    e[3]  = -0.48860251190291987f * x;
    e[4]  = 1.0925484305920792f * xy;
    e[5]  = -1.0925484305920792f * yz;
    e[6]  = 0.94617469575756f * zz - 0.31539156525252005f;
    e[7]  = -1.0925484305920792f * xz;
    e[8]  = 0.5462742152960396f * (xx - yy);
    e[9]  = 0.5900435899266435f * y * (3.0f * xx - yy);
    e[10] = 2.890611442640554f * xy * z;
    e[11] = 0.4570457994644657f * y * (4.0f * zz - xx - yy);
    e[12] = 0.3731763325901154f * z * (2.0f * zz - 3.0f * xx - 3.0f * yy);
    e[13] = 0.4570457994644657f * x * (4.0f * zz - xx - yy);
    e[14] = 1.445305721320277f * z * (xx - yy);
    e[15] = 0.5900435899266435f * x * (xx - 3.0f * yy);
}

// ---------------- smem layout (floats) ----------------
#define SM_BUFA  19072              // [128][68] inputs; geo cols 0..15; col2 partial cols 32..47
#define SM_SIGH  27776              // [128][68] sig_h; later col1_h
#define SM_VISH  36480              // [128][68] vis_h; later vis1 tile
#define SM_COLH  45184              // [128][68] col0_h; later col2 partial
#define SM_VIS   53888              // [128]
#define SM_TOTAL 54016
#define SMEM_BYTES (SM_TOTAL * 4)

typedef wmma::fragment<wmma::matrix_a, 16, 16, 8, wmma::precision::tf32, wmma::row_major> FragA;
typedef wmma::fragment<wmma::matrix_b, 16, 16, 8, wmma::precision::tf32, wmma::row_major> FragB;
typedef wmma::fragment<wmma::accumulator, 16, 16, 8, float> FragC;

// group barrier: 128 threads, barrier id g+1 (4 groups of 4 warps)
#define GBAR() asm volatile("bar.sync %0, %1;" :: "r"(g + 1), "r"(128) : "memory")

__global__ void __launch_bounds__(512, 1)
nerf_wmma(const float* __restrict__ x_feat, const float* __restrict__ dvec,
          const float* __restrict__ lvec, float* __restrict__ out,
          int N, int ntiles) {
    extern __shared__ float sm[];
    float* sW   = sm;
    float* bufA = sm + SM_BUFA;
    float* sigH = sm + SM_SIGH;
    float* visH = sm + SM_VISH;
    float* colH = sm + SM_COLH;
    float* visR = sm + SM_VIS;

    int tid = threadIdx.x, wid = tid >> 5;
    int g  = wid >> 2;              // group 0..3, 4 warps each, 32 rows each
    int w4 = wid & 3;
    int blk = w4 >> 1, h = w4 & 1;
    int rowM = g * 32 + blk * 16;   // this warp's 16-row block
    int t2 = tid & 127;             // thread id within group

    {
        const float4* s = (const float4*)g_W;
        float4* d = (float4*)sW;
        for (int i = tid; i < W_TOTAL / 4; i += 512) d[i] = s[i];
    }
    __syncthreads();

    for (int tile = blockIdx.x; tile < ntiles; tile += gridDim.x) {
        // ---- phase 0: group fills its 32 rows of bufA ----
        {
            int r = g * 32 + (t2 & 31);
            int p = tile * 128 + r;
            int pc = (p < N) ? p : (N - 1);
            if (t2 < 32) {
                const float4* xp = (const float4*)(x_feat + 32 * (size_t)pc);
                float* dst = bufA + r * 68;
#pragma unroll
                for (int i = 0; i < 8; i++) {
                    float4 v = xp[i];
                    dst[4 * i]     = tf32r(v.x);
                    dst[4 * i + 1] = tf32r(v.y);
                    dst[4 * i + 2] = tf32r(v.z);
                    dst[4 * i + 3] = tf32r(v.w);
                }
            } else if (t2 < 64) {
                float e[16];
                const float* lp = lvec + 3 * (size_t)pc;
                sh16(lp[0], lp[1], lp[2], e);
                float* dst = bufA + r * 68 + 32;
#pragma unroll
                for (int i = 0; i < 16; i++) dst[i] = tf32r(e[i]);
            } else if (t2 < 96) {
                float e[16];
                const float* dp = dvec + 3 * (size_t)pc;
                sh16(dp[0], dp[1], dp[2], e);
                float* dst = bufA + r * 68 + 48;
#pragma unroll
                for (int i = 0; i < 16; i++) dst[i] = tf32r(e[i]);
            }
        }
        GBAR();

        // ---- phase 1: A frags hoisted, one accumulator live at a time ----
        {
            FragA a[8];
#pragma unroll
            for (int k = 0; k < 8; k++)
                wmma::load_matrix_sync(a[k], bufA + rowM * 68 + k * 8, 68);
#pragma unroll
            for (int t = 0; t < 2; t++) {
                int nt = 2 * h + t;
                {   // sig0 (K=32)
                    FragC c; wmma::fill_fragment(c, 0.f);
#pragma unroll
                    for (int k = 0; k < 4; k++) {
                        FragB b;
                        wmma::load_matrix_sync(b, sW + OFF_SIG0 + k * 8 * 68 + nt * 16, 68);
                        wmma::mma_sync(c, a[k], b, c);
                    }
#pragma unroll
                    for (int i = 0; i < c.num_elements; i++) c.x[i] = tf32r(fmaxf(c.x[i], 0.f));
                    wmma::store_matrix_sync(sigH + rowM * 68 + nt * 16, c, 68, wmma::mem_row_major);
                }
                {   // vis0 (K=48)
                    FragC c; wmma::fill_fragment(c, 0.f);
#pragma unroll
                    for (int k = 0; k < 6; k++) {
                        FragB b;
                        wmma::load_matrix_sync(b, sW + OFF_VIS0 + k * 8 * 68 + nt * 16, 68);
                        wmma::mma_sync(c, a[k], b, c);
                    }
#pragma unroll
                    for (int i = 0; i < c.num_elements; i++) c.x[i] = tf32r(fmaxf(c.x[i], 0.f));
                    wmma::store_matrix_sync(visH + rowM * 68 + nt * 16, c, 68, wmma::mem_row_major);
                }
                {   // col0 (K=64)
                    FragC c; wmma::fill_fragment(c, 0.f);
#pragma unroll
                    for (int k = 0; k < 8; k++) {
                        FragB b;
                        wmma::load_matrix_sync(b, sW + OFF_COL0 + k * 8 * 68 + nt * 16, 68);
                        wmma::mma_sync(c, a[k], b, c);
                    }
#pragma unroll
                    for (int i = 0; i < c.num_elements; i++) c.x[i] = tf32r(fmaxf(c.x[i], 0.f));
                    wmma::store_matrix_sync(colH + rowM * 68 + nt * 16, c, 68, wmma::mem_row_major);
                }
            }
        }
        GBAR();

        // ---- phase 2: h==0 -> sig1 (geo -> bufA cols 0..15); h==1 -> vis1 ----
        {
            const float* Ain = h ? visH : sigH;
            const float* Bw  = h ? (sW + OFF_VIS1) : (sW + OFF_SIG1);
            FragA a[8];
#pragma unroll
            for (int k = 0; k < 8; k++)
                wmma::load_matrix_sync(a[k], Ain + rowM * 68 + k * 8, 68);
            FragC c;
            wmma::fill_fragment(c, 0.f);
#pragma unroll
            for (int k = 0; k < 8; k++) {
                FragB b;
                wmma::load_matrix_sync(b, Bw + k * 8 * 20, 20);
                wmma::mma_sync(c, a[k], b, c);
            }
            if (h == 0) {   // geo: tf32-round, NO relu
#pragma unroll
                for (int i = 0; i < c.num_elements; i++) c.x[i] = tf32r(c.x[i]);
                wmma::store_matrix_sync(bufA + rowM * 68, c, 68, wmma::mem_row_major);
            } else {        // vis raw logit (col 0 real)
                wmma::store_matrix_sync(visH + rowM * 68, c, 68, wmma::mem_row_major);
            }
        }
        GBAR();
        if (t2 < 32) {
            int r = g * 32 + t2;
            visR[r] = __fdividef(1.f, 1.f + __expf(-visH[r * 68]));
        }

        // ---- phase 3: col1 = relu(col0_h @ C1A + geo @ C1B) -> sigH ----
        {
            FragA a1[8], a2[2];
#pragma unroll
            for (int k = 0; k < 8; k++)
                wmma::load_matrix_sync(a1[k], colH + rowM * 68 + k * 8, 68);
#pragma unroll
            for (int k = 0; k < 2; k++)
                wmma::load_matrix_sync(a2[k], bufA + rowM * 68 + k * 8, 68);
#pragma unroll
            for (int t = 0; t < 2; t++) {
                int nt = 2 * h + t;
                FragC c; wmma::fill_fragment(c, 0.f);
#pragma unroll
                for (int k = 0; k < 8; k++) {
                    FragB b;
                    wmma::load_matrix_sync(b, sW + OFF_C1A + k * 8 * 68 + nt * 16, 68);
                    wmma::mma_sync(c, a1[k], b, c);
                }
#pragma unroll
                for (int k = 0; k < 2; k++) {
                    FragB b;
                    wmma::load_matrix_sync(b, sW + OFF_C1B + k * 8 * 68 + nt * 16, 68);
                    wmma::mma_sync(c, a2[k], b, c);
                }
#pragma unroll
                for (int i = 0; i < c.num_elements; i++) c.x[i] = tf32r(fmaxf(c.x[i], 0.f));
                wmma::store_matrix_sync(sigH + rowM * 68 + nt * 16, c, 68, wmma::mem_row_major);
            }
        }
        GBAR();

        // ---- phase 4: col2, split-k across h: h==0 k0..3 -> colH; h==1 k4..7 -> bufA+32
        {
            FragA a[4];
#pragma unroll
            for (int k = 0; k < 4; k++)
                wmma::load_matrix_sync(a[k], sigH + rowM * 68 + (h * 4 + k) * 8, 68);
            FragC c;
            wmma::fill_fragment(c, 0.f);
#pragma unroll
            for (int k = 0; k < 4; k++) {
                FragB b;
                wmma::load_matrix_sync(b, sW + OFF_COL2 + (h * 4 + k) * 8 * 20, 20);
                wmma::mma_sync(c, a[k], b, c);
            }
            float* dst = h ? (bufA + rowM * 68 + 32) : (colH + rowM * 68);
            wmma::store_matrix_sync(dst, c, 68, wmma::mem_row_major);
        }
        GBAR();

        // ---- epilogue: color = relu(p0+p1) * sigmoid(vis), group's 32 rows ----
        for (int i = t2; i < 96; i += 128) {
            int pp = g * 32 + i / 3, c = i % 3;
            int gg = tile * 128 + pp;
            if (gg < N) {
                float v = colH[pp * 68 + c] + bufA[pp * 68 + 32 + c];
                out[3 * (size_t)gg + c] = fmaxf(v, 0.f) * visR[pp];
            }
        }
        GBAR();
    }
}

extern "C" void kernel_launch(void* const* d_in, const int* in_sizes, int n_in,
                              void* d_out, int out_size) {
    const float* x_feat = (const float*)d_in[0];
    const float* dv     = (const float*)d_in[1];
    const float* lv     = (const float*)d_in[2];
    const float* w_sig0 = (const float*)d_in[3];
    const float* w_sig1 = (const float*)d_in[4];
    const float* w_col0 = (const float*)d_in[5];
    const float* w_col1 = (const float*)d_in[6];
    const float* w_col2 = (const float*)d_in[7];
    const float* w_vis0 = (const float*)d_in[8];
    const float* w_vis1 = (const float*)d_in[9];
    float* out = (float*)d_out;
    int N = in_sizes[0] / 32;
    int ntiles = (N + 127) / 128;

    int dev = 0, smc = 148;
    cudaGetDevice(&dev);
    cudaDeviceGetAttribute(&smc, cudaDevAttrMultiProcessorCount, dev);
    int grid = (smc < ntiles) ? smc : ntiles;

    cudaFuncSetAttribute(nerf_wmma, cudaFuncAttributeMaxDynamicSharedMemorySize,
                         SMEM_BYTES);

    prep_kernel<<<1, 256>>>(w_sig0, w_sig1, w_col0, w_col1, w_col2, w_vis0, w_vis1);
    nerf_wmma<<<grid, 512, SMEM_BYTES>>>(x_feat, dv, lv, out, N, ntiles);
}